// round 15
// baseline (speedup 1.0000x reference)
#include <cuda_runtime.h>
#include <cuda_fp16.h>
#include <cstdint>
#include <cstddef>

#define T_STEPS 512
#define BATCH   64
#define HID     1024
#define G4      4096
#define M1      (T_STEPS * BATCH)   // 32768
#define NREC    64                   // recurrence CTAs

// ---------------- device scratch (no allocs allowed) ----------------
__device__ float    g_xpre[(size_t)M1 * G4];      // 512 MB: [T*B, 4H]
__device__ __half   g_a16[(size_t)M1 * HID];      // 64 MB: input in fp16
__device__ __half   g_w16[(size_t)G4 * HID];      // 8 MB: W_ih in fp16
__device__ __half   g_hbuf[2][BATCH * HID];       // double-buffered h, fp16 A-fragment-major
__device__ unsigned g_cnt1[8];                    // tree barrier: 8 groups of 8 CTAs
__device__ unsigned g_cnt2;                       // tree barrier root
__device__ unsigned g_gen;                        // monotonic generation

// ---------------- helpers ----------------
__device__ __forceinline__ void mma_f16(float* c, const uint32_t* a, const uint32_t* b) {
    asm volatile(
        "mma.sync.aligned.m16n8k16.row.col.f32.f16.f16.f32 "
        "{%0,%1,%2,%3}, {%4,%5,%6,%7}, {%8,%9}, {%0,%1,%2,%3};"
        : "+f"(c[0]), "+f"(c[1]), "+f"(c[2]), "+f"(c[3])
        : "r"(a[0]), "r"(a[1]), "r"(a[2]), "r"(a[3]), "r"(b[0]), "r"(b[1]));
}

__device__ __forceinline__ void cp_async16(uint32_t saddr, const void* gaddr) {
    asm volatile("cp.async.cg.shared.global [%0], [%1], 16;\n"
                 :: "r"(saddr), "l"(gaddr));
}
#define CP_COMMIT() asm volatile("cp.async.commit_group;\n" ::: "memory")
#define CP_WAIT1()  asm volatile("cp.async.wait_group 1;\n" ::: "memory")

__device__ __forceinline__ uint32_t h2bits(float a, float b) {
    __half2 h = __floats2half2_rn(a, b);
    return *(uint32_t*)&h;
}

// ---------------- phase 0: fp32 -> fp16 conversion (input, W_ih) ----------------
__global__ __launch_bounds__(256) void cvt_k(const float* __restrict__ A,
                                             const float* __restrict__ W) {
    const int nthr = gridDim.x * blockDim.x;
    const int tid0 = blockIdx.x * blockDim.x + threadIdx.x;
    for (size_t i = tid0; i < (size_t)M1 * HID / 4; i += nthr) {
        float4 v = *(const float4*)(A + i * 4);
        uint2 o; o.x = h2bits(v.x, v.y); o.y = h2bits(v.z, v.w);
        *(uint2*)&g_a16[i * 4] = o;
    }
    for (size_t i = tid0; i < (size_t)G4 * HID / 4; i += nthr) {
        float4 v = *(const float4*)(W + i * 4);
        uint2 o; o.x = h2bits(v.x, v.y); o.y = h2bits(v.z, v.w);
        *(uint2*)&g_w16[i * 4] = o;
    }
}

// ---------------- phase 1: x_pre = input @ W_ih^T + b_ih + b_hh (fp16, cp.async ring-3) ----------------
#define G1_STRIDE_W 20
#define G1_STAGE_W  (128 * G1_STRIDE_W)
__global__ __launch_bounds__(256, 2) void gemm1_k(
    const float* __restrict__ bih, const float* __restrict__ bhh) {
    extern __shared__ uint32_t sm1[];
    uint32_t* As = sm1;
    uint32_t* Bs = sm1 + 3 * G1_STAGE_W;

    const int tid   = threadIdx.x;
    const int lane  = tid & 31;
    const int wid   = tid >> 5;
    const int warpM = wid & 3;
    const int warpN = wid >> 2;
    const int m0 = blockIdx.y * 128;
    const int n0 = blockIdx.x * 128;

    const int g  = lane >> 2;
    const int tg = lane & 3;

    const uint32_t as_b = (uint32_t)__cvta_generic_to_shared(As);
    const uint32_t bs_b = (uint32_t)__cvta_generic_to_shared(Bs);

    const int lr0 = (tid * 2) >> 2;
    const int lg0 = (tid * 2) & 3;
    const int lr1 = (tid * 2 + 1) >> 2;
    const int lg1 = (tid * 2 + 1) & 3;
    const char* Asrc0 = (const char*)g_a16 + (size_t)(m0 + lr0) * 2048 + lg0 * 16;
    const char* Asrc1 = (const char*)g_a16 + (size_t)(m0 + lr1) * 2048 + lg1 * 16;
    const char* Wsrc0 = (const char*)g_w16 + (size_t)(n0 + lr0) * 2048 + lg0 * 16;
    const char* Wsrc1 = (const char*)g_w16 + (size_t)(n0 + lr1) * 2048 + lg1 * 16;
    const uint32_t ad0 = as_b + (uint32_t)(lr0 * 80 + lg0 * 16);
    const uint32_t ad1 = as_b + (uint32_t)(lr1 * 80 + lg1 * 16);
    const uint32_t bd0 = bs_b + (uint32_t)(lr0 * 80 + lg0 * 16);
    const uint32_t bd1 = bs_b + (uint32_t)(lr1 * 80 + lg1 * 16);

    float acc[2][8][4];
#pragma unroll
    for (int mt = 0; mt < 2; mt++)
#pragma unroll
        for (int nt = 0; nt < 8; nt++)
#pragma unroll
            for (int r = 0; r < 4; r++) acc[mt][nt][r] = 0.0f;

#pragma unroll
    for (int pc = 0; pc < 2; pc++) {
        const uint32_t so = (uint32_t)(pc * G1_STAGE_W * 4);
        cp_async16(ad0 + so, Asrc0 + pc * 64);
        cp_async16(ad1 + so, Asrc1 + pc * 64);
        cp_async16(bd0 + so, Wsrc0 + pc * 64);
        cp_async16(bd1 + so, Wsrc1 + pc * 64);
        CP_COMMIT();
    }

    for (int c = 0; c < 32; c++) {
        CP_WAIT1();
        __syncthreads();
        if (c + 2 < 32) {
            const uint32_t so = (uint32_t)(((c + 2) % 3) * G1_STAGE_W * 4);
            cp_async16(ad0 + so, Asrc0 + (c + 2) * 64);
            cp_async16(ad1 + so, Asrc1 + (c + 2) * 64);
            cp_async16(bd0 + so, Wsrc0 + (c + 2) * 64);
            cp_async16(bd1 + so, Wsrc1 + (c + 2) * 64);
        }
        CP_COMMIT();

        const uint32_t* Ac = As + (c % 3) * G1_STAGE_W;
        const uint32_t* Bc = Bs + (c % 3) * G1_STAGE_W;
#pragma unroll
        for (int ksl = 0; ksl < 2; ksl++) {
            const int kb = ksl * 8;
            uint32_t af[2][4];
#pragma unroll
            for (int mt = 0; mt < 2; mt++) {
                const int mb = warpM * 32 + mt * 16;
                af[mt][0] = Ac[(mb + g) * G1_STRIDE_W + kb + tg];
                af[mt][1] = Ac[(mb + 8 + g) * G1_STRIDE_W + kb + tg];
                af[mt][2] = Ac[(mb + g) * G1_STRIDE_W + kb + tg + 4];
                af[mt][3] = Ac[(mb + 8 + g) * G1_STRIDE_W + kb + tg + 4];
            }
#pragma unroll
            for (int nt = 0; nt < 8; nt++) {
                const int nb = warpN * 64 + nt * 8;
                uint32_t bf[2];
                bf[0] = Bc[(nb + g) * G1_STRIDE_W + kb + tg];
                bf[1] = Bc[(nb + g) * G1_STRIDE_W + kb + tg + 4];
                mma_f16(acc[0][nt], af[0], bf);
                mma_f16(acc[1][nt], af[1], bf);
            }
        }
    }

#pragma unroll
    for (int nt = 0; nt < 8; nt++) {
        const int col = n0 + warpN * 64 + nt * 8 + 2 * tg;
        const float bias0 = bih[col] + bhh[col];
        const float bias1 = bih[col + 1] + bhh[col + 1];
#pragma unroll
        for (int mt = 0; mt < 2; mt++) {
            const int row = m0 + warpM * 32 + mt * 16 + g;
            float2 v0; v0.x = acc[mt][nt][0] + bias0; v0.y = acc[mt][nt][1] + bias1;
            *(float2*)&g_xpre[(size_t)row * G4 + col] = v0;
            float2 v1; v1.x = acc[mt][nt][2] + bias0; v1.y = acc[mt][nt][3] + bias1;
            *(float2*)&g_xpre[(size_t)(row + 8) * G4 + col] = v1;
        }
    }
}

// ---------------- grid-wide barrier: two-level tree (64 CTAs), self-resetting ----------------
__device__ __forceinline__ void gbar(int cta) {
    __syncthreads();
    if (threadIdx.x == 0) {
        volatile unsigned* vgen = &g_gen;
        const unsigned gen0 = *vgen;
        __threadfence();
        const int grp = cta >> 3;
        if (atomicAdd(&g_cnt1[grp], 1u) == 7u) {
            g_cnt1[grp] = 0u;
            __threadfence();
            if (atomicAdd(&g_cnt2, 1u) == 7u) {
                g_cnt2 = 0u;
                __threadfence();
                *vgen = gen0 + 1u;
            } else {
                while (*vgen == gen0) { __nanosleep(16); }
            }
        } else {
            while (*vgen == gen0) { __nanosleep(16); }
        }
    }
    __syncthreads();
}

// ---------------- fp16 A-fragment addressing ----------------
// h element (b,k): byte offset = ((mt*64+ks)*32 + lane)*16 + j*4 + half*2
__device__ __forceinline__ uint32_t hfrag_off(int b, int k) {
    return (uint32_t)((((b >> 4) * 64 + (k >> 4)) * 32 + (b & 7) * 4 + ((k >> 1) & 3)) * 16
                      + (((k >> 3) & 1) * 2 + ((b >> 3) & 1)) * 4 + (k & 1) * 2);
}

// ---------------- phase 2: persistent recurrence (fp16 mma, 64 fat CTAs) ----------------
// 64 CTAs x 256 threads (8 warps). CTA owns 64 gate-cols: {g*1024 + cta*16 + u}, u in 0..15.
// Warp w: kh=w>>1 owns ks in [kh*16, kh*16+16); mtp=w&1 owns m-tiles {2mtp, 2mtp+1};
// each warp covers ALL 8 n-tiles (W fragment reuse doubled; A staging unchanged).
// A staged via cp.async ring-2 (2 KB chunks). 4 partial buffers; gate phase 4 cells/thread.
#define PRE_STRIDE 66
#define PRE_BUF    (64 * PRE_STRIDE)
__global__ __launch_bounds__(256) void lstm_rec_k(
    const float* __restrict__ Whh, const float* __restrict__ h0,
    const float* __restrict__ c0, float* __restrict__ out) {
    extern __shared__ uint32_t smem[];
    uint32_t* W_s   = smem;                          // 32768 u32 (128 KB) fp16 b-fragments
    float*    pre_s = (float*)(smem + 32768);        // 4 x [64][66] = 67584 B
    uint32_t* hs    = smem + 32768 + 4 * PRE_BUF;    // 8 warps x 2 x 2KB = 32 KB

    const int tid    = threadIdx.x;
    const int lane   = tid & 31;
    const int w      = tid >> 5;                     // 0..7
    const int kh     = w >> 1;                       // K quarter (0..3)
    const int mtp    = w & 1;                        // m-pair (0..1)
    const int cta    = blockIdx.x;
    const int hcbase = cta * 16;

    const uint32_t hs_w = (uint32_t)__cvta_generic_to_shared(hs) + w * 4096 + lane * 16;

    // ---- fill W b-fragments (one-time), fp16: 8 n-tiles x 64 ks x 32 lanes ----
    for (int e = tid; e < 16384; e += 256) {
        const int li = e & 31;
        const int ks = (e >> 5) & 63;
        const int nt = e >> 11;                      // 0..7
        const int g  = li >> 2;
        const int tg = li & 3;
        const int j  = nt * 8 + g;                   // gate-col 0..63
        const float* wr = Whh + (size_t)((j >> 4) * HID + hcbase + (j & 15)) * HID + ks * 16 + 2 * tg;
        W_s[e * 2]     = h2bits(__ldg(wr),     __ldg(wr + 1));
        W_s[e * 2 + 1] = h2bits(__ldg(wr + 8), __ldg(wr + 9));
    }

    // ---- cell ownership: thread owns hcol u, batches {bq, bq+16, bq+32, bq+48} ----
    const int u  = tid & 15;
    const int bq = tid >> 4;                         // 0..15

    float c_r[4], h_r[4];
#pragma unroll
    for (int j = 0; j < 4; j++) {
        const int b   = bq + 16 * j;
        const int idx = b * HID + hcbase + u;
        c_r[j] = c0[idx];
        const float h = h0[idx];
        h_r[j] = h;
        *(__half*)((char*)g_hbuf[0] + hfrag_off(b, hcbase + u)) = __float2half_rn(h);
    }

    gbar(cta);

    const int ks0 = kh * 16;

    for (int t = 0; t < T_STEPS; t++) {
        const char*  hin = (const char*)g_hbuf[t & 1];
        __half*     hout = g_hbuf[(t + 1) & 1];

        // ---- prefetch x_pre (independent of h; hidden under mma) ----
        float xpv[4][4];
        {
            const float* xp = g_xpre + (size_t)t * BATCH * G4;
#pragma unroll
            for (int j = 0; j < 4; j++) {
                const float* xb = xp + (size_t)(bq + 16 * j) * G4 + hcbase + u;
                xpv[j][0] = __ldg(xb);
                xpv[j][1] = __ldg(xb + HID);
                xpv[j][2] = __ldg(xb + 2 * HID);
                xpv[j][3] = __ldg(xb + 3 * HID);
            }
        }

        float acc[2][8][4];                          // [mtl][n][reg]
#pragma unroll
        for (int m = 0; m < 2; m++)
#pragma unroll
            for (int n = 0; n < 8; n++)
#pragma unroll
                for (int r = 0; r < 4; r++) acc[m][n][r] = 0.0f;

        const char* hb = hin + lane * 16;

        // ring-2: chunk = 2 ks x 2 mtl = 2 KB into slot kc&1; prologue: chunk 0
        {
#pragma unroll
            for (int c = 0; c < 2; c++)
#pragma unroll
                for (int mtl = 0; mtl < 2; mtl++)
                    cp_async16(hs_w + (c * 2 + mtl) * 512,
                               hb + (size_t)(((mtp * 2 + mtl) * 64 + ks0 + c) * 512));
            CP_COMMIT();
        }

#pragma unroll
        for (int kc = 0; kc < 8; kc++) {
            if (kc < 7) {
                const int kc2 = kc + 1;
                const uint32_t dst = hs_w + (kc2 & 1) * 2048;
#pragma unroll
                for (int c = 0; c < 2; c++)
#pragma unroll
                    for (int mtl = 0; mtl < 2; mtl++)
                        cp_async16(dst + (c * 2 + mtl) * 512,
                                   hb + (size_t)(((mtp * 2 + mtl) * 64 + ks0 + kc2 * 2 + c) * 512));
                CP_COMMIT();
                CP_WAIT1();            // chunk kc resident (kc+1 outstanding)
            } else {
                asm volatile("cp.async.wait_group 0;\n" ::: "memory");
            }
            __syncwarp();

            const uint32_t bufb = hs_w + (kc & 1) * 2048;
#pragma unroll
            for (int c = 0; c < 2; c++) {
                const int ksg = ks0 + kc * 2 + c;
                uint32_t af0[4], af1[4];
                asm volatile("ld.shared.v4.b32 {%0,%1,%2,%3}, [%4];"
                             : "=r"(af0[0]), "=r"(af0[1]), "=r"(af0[2]), "=r"(af0[3])
                             : "r"(bufb + (c * 2 + 0) * 512));
                asm volatile("ld.shared.v4.b32 {%0,%1,%2,%3}, [%4];"
                             : "=r"(af1[0]), "=r"(af1[1]), "=r"(af1[2]), "=r"(af1[3])
                             : "r"(bufb + (c * 2 + 1) * 512));
#pragma unroll
                for (int n = 0; n < 8; n++) {
                    const uint2 bv = *(const uint2*)&W_s[((n * 64 + ksg) * 32 + lane) * 2];
                    mma_f16(acc[0][n], af0, (const uint32_t*)&bv);
                    mma_f16(acc[1][n], af1, (const uint32_t*)&bv);
                }
            }
        }

        // publish partials to this K-quarter's buffer (rows disjoint between mtp warps)
        {
            float* pb = pre_s + kh * PRE_BUF;
            const int rg = lane >> 2;
            const int cg = 2 * (lane & 3);
#pragma unroll
            for (int mtl = 0; mtl < 2; mtl++) {
                const int rb = (mtp * 2 + mtl) * 16 + rg;
#pragma unroll
                for (int n = 0; n < 8; n++) {
                    const int colb = n * 8 + cg;
                    float2 v0; v0.x = acc[mtl][n][0]; v0.y = acc[mtl][n][1];
                    *(float2*)&pb[rb * PRE_STRIDE + colb] = v0;
                    float2 v1; v1.x = acc[mtl][n][2]; v1.y = acc[mtl][n][3];
                    *(float2*)&pb[(rb + 8) * PRE_STRIDE + colb] = v1;
                }
            }
        }
        __syncthreads();

        // gate math + h/c update + stores (4 cells per thread); sum 4 partials
        float* orow = out + (size_t)t * BATCH * HID;
#pragma unroll
        for (int j = 0; j < 4; j++) {
            const int b = bq + 16 * j;
            float pi = xpv[j][0], pf = xpv[j][1], po = xpv[j][2], pg = xpv[j][3];
#pragma unroll
            for (int p = 0; p < 4; p++) {
                const float* pb = &pre_s[p * PRE_BUF + b * PRE_STRIDE];
                pi += pb[u];
                pf += pb[16 + u];
                po += pb[32 + u];
                pg += pb[48 + u];
            }
            const float ig = 1.0f / (1.0f + __expf(-pi));
            const float fg = 1.0f / (1.0f + __expf(-pf));
            const float og = 1.0f / (1.0f + __expf(-po));
            c_r[j] = fg * c_r[j] + ig * tanhf(pg);
            const float h = og * tanhf(c_r[j]);
            h_r[j] = h;
            *(__half*)((char*)hout + hfrag_off(b, hcbase + u)) = __float2half_rn(h);
            orow[b * HID + hcbase + u] = h;
        }

        gbar(cta);
    }

    // finals: out = [output | h_f | c_f]
    float* hf = out + (size_t)T_STEPS * BATCH * HID;
    float* cf = hf + BATCH * HID;
#pragma unroll
    for (int j = 0; j < 4; j++) {
        const int b = bq + 16 * j;
        hf[b * HID + hcbase + u] = h_r[j];
        cf[b * HID + hcbase + u] = c_r[j];
    }
}

// ---------------- launch ----------------
extern "C" void kernel_launch(void* const* d_in, const int* in_sizes, int n_in,
                              void* d_out, int out_size) {
    const float* input = (const float*)d_in[0];   // [T, B, I]
    const float* h0    = (const float*)d_in[1];   // [1, B, H]
    const float* c0    = (const float*)d_in[2];   // [1, B, H]
    const float* W_ih  = (const float*)d_in[3];   // [4H, I]
    const float* b_ih  = (const float*)d_in[4];   // [4H]
    const float* W_hh  = (const float*)d_in[5];   // [4H, H]
    const float* b_hh  = (const float*)d_in[6];   // [4H]
    float* out = (float*)d_out;

    const int g1_smem  = 6 * G1_STAGE_W * 4;                 // 61440 B
    const int rec_smem = 131072 + 4 * PRE_BUF * 4 + 32768;   // 231424 B
    cudaFuncSetAttribute(gemm1_k, cudaFuncAttributeMaxDynamicSharedMemorySize, g1_smem);
    cudaFuncSetAttribute(lstm_rec_k, cudaFuncAttributeMaxDynamicSharedMemorySize, rec_smem);

    cvt_k<<<2048, 256>>>(input, W_ih);
    dim3 g1(G4 / 128, M1 / 128);   // (32, 256)
    gemm1_k<<<g1, 256, g1_smem>>>(b_ih, b_hh);
    lstm_rec_k<<<NREC, 256, rec_smem>>>(W_hh, h0, c0, out);
}